// round 15
// baseline (speedup 1.0000x reference)
#include <cuda_runtime.h>
#include <cuda_bf16.h>
#include <cstdint>

// ---------------------------------------------------------------------------
// Problem constants
// ---------------------------------------------------------------------------
#define BB      2
#define LL      2048
#define ROWS    (BB*LL)        // 4096 tokens
#define DM      256            // d_model
#define DI      512            // d_inner
#define DS      16             // d_state
#define DR      16             // dt_rank
#define NL      16             // layers
#define NC      64             // scan chunks per sequence
#define CT      (LL/NC)        // 32 steps per chunk
#define NDT     544            // fused dt|B|C GEMM width (512 + 32)
#define LOG2E   1.44269504f

// ---------------------------------------------------------------------------
// Scratch (static device allocations — no cudaMalloc allowed)
// ---------------------------------------------------------------------------
__device__ float g_h  [ROWS*DM];     // block output / embedding
__device__ float g_res[ROWS*DM];     // residual stream
__device__ float g_hn [ROWS*DM];     // normed input
__device__ float g_xz [ROWS*2*DI];   // in_proj output (x | silu(z))
__device__ float g_xc [ROWS*DI];     // conv+silu output
__device__ float g_dbc[ROWS*32];     // B | C per token
__device__ float g_dt [ROWS*DI];     // softplus(dt)  (fallback path only)
__device__ float g_ce [ROWS*DI*2];   // (c = dt*x, E = exp(-dt)) interleaved
__device__ float g_y  [ROWS*DI];     // scan output * silu(z)
__device__ float g_ap [BB*DI*DS*NC]; // chunk prod(dA)
__device__ float g_hl [BB*DI*DS*NC]; // chunk local h final
__device__ float g_hi [BB*DI*DS*NC]; // chunk initial h
__device__ float g_wall[NL*NDT*DI];  // fused (W_dt | xw_B | xw_C) weights
__device__ float g_Aall[NL*DI*DS];   // precomputed A = -exp(A_log)
__device__ float g_fastf[NL*DI];     // 1.0 if S4D fast path valid for (l,d)

// ---------------------------------------------------------------------------
// FMA-pipe fast math (avoids MUFU bottleneck)
// ---------------------------------------------------------------------------
__device__ __forceinline__ float fexp2(float x) {
    x = fminf(fmaxf(x, -125.f), 127.f);
    float t = x + 12582912.f;              // 1.5 * 2^23 round trick
    int   i = __float_as_int(t) - 0x4B400000;   // rint(x)
    float f = x - (t - 12582912.f);             // frac in [-0.5, 0.5]
    float p = 1.54035304e-4f;
    p = fmaf(p, f, 1.33335581e-3f);
    p = fmaf(p, f, 9.61812911e-3f);
    p = fmaf(p, f, 5.55041087e-2f);
    p = fmaf(p, f, 2.40226507e-1f);
    p = fmaf(p, f, 6.93147181e-1f);
    p = fmaf(p, f, 1.0f);
    return p * __int_as_float((i + 127) << 23);
}
__device__ __forceinline__ float fsilu(float v) {
    return __fdividef(v, 1.f + fexp2(-LOG2E * v));
}
__device__ __forceinline__ float fsoftplus(float v) {
    if (v > 15.f) return v;
    return log1pf(fexp2(LOG2E * v));
}
__device__ __forceinline__ uint32_t f2tf(float f) {
    uint32_t u; asm("cvt.rna.tf32.f32 %0, %1;" : "=r"(u) : "f"(f)); return u;
}
__device__ __forceinline__ void mma8(float* c, const uint32_t* a, const uint32_t* b) {
    asm volatile(
        "mma.sync.aligned.m16n8k8.row.col.f32.tf32.tf32.f32 "
        "{%0,%1,%2,%3}, {%4,%5,%6,%7}, {%8,%9}, {%0,%1,%2,%3};"
        : "+f"(c[0]), "+f"(c[1]), "+f"(c[2]), "+f"(c[3])
        : "r"(a[0]), "r"(a[1]), "r"(a[2]), "r"(a[3]), "r"(b[0]), "r"(b[1]));
}

// ---------------------------------------------------------------------------
// Embedding gather
// ---------------------------------------------------------------------------
__global__ void embed_k(const int* __restrict__ ids,
                        const float* __restrict__ emb) {
    int row = blockIdx.x, t = threadIdx.x;
    g_h[(size_t)row*DM + t] = emb[(size_t)ids[row]*DM + t];
}

// ---------------------------------------------------------------------------
// A precompute: g_Aall = -exp(A_log); g_fastf = S4D pattern check.
// ---------------------------------------------------------------------------
__global__ void aprep_k(const float* __restrict__ A_log) {
    int i = blockIdx.x*256 + threadIdx.x;     // 0..NL*DI
    const float* src = A_log + (size_t)i*DS;
    float A[DS];
    #pragma unroll
    for (int s = 0; s < DS; s++) A[s] = -__expf(src[s]);
    bool fast = fabsf(A[0] + 1.f) <= 1e-4f;
    #pragma unroll
    for (int s = 1; s < DS; s++)
        fast = fast && (fabsf(A[s] - (float)(s+1)*A[0]) <= 1e-3f*fabsf(A[s]));
    #pragma unroll
    for (int s = 0; s < DS; s++) g_Aall[(size_t)i*DS + s] = A[s];
    g_fastf[i] = fast ? 1.f : 0.f;
}

// ---------------------------------------------------------------------------
// Fused weight precompute: W_dt = dtw @ xw[0:16] ; rows 512.. = xw B/C rows
// ---------------------------------------------------------------------------
__global__ void wdt_k(const float* __restrict__ xw,
                      const float* __restrict__ dtw) {
    size_t i = (size_t)blockIdx.x*256 + threadIdx.x;
    int k = (int)(i & (DI-1));
    int n = (int)((i >> 9) % NDT);
    int l = (int)(i / ((size_t)NDT*DI));
    const float* xwl = xw + (size_t)l*48*DI;
    float v;
    if (n < DI) {
        const float* dr = dtw + ((size_t)l*DI + n)*DR;
        v = 0.f;
        #pragma unroll
        for (int r = 0; r < DR; r++) v += dr[r] * xwl[(size_t)r*DI + k];
    } else {
        v = xwl[(size_t)(16 + n - DI)*DI + k];
    }
    g_wall[i] = v;
}

// ---------------------------------------------------------------------------
// residual += h (or res = h when first); hn = rmsnorm(res) * w
// Warp-per-row: 8 rows per 256-thread block, 8 elems/lane, shfl-only
// reduction, no __syncthreads (was 7.9us latency-bound with 1 elem/thread).
// ---------------------------------------------------------------------------
__global__ __launch_bounds__(256)
void norm_k(const float* __restrict__ w, int first) {
    int warp = threadIdx.x >> 5, lane = threadIdx.x & 31;
    int row  = blockIdx.x*8 + warp;
    size_t base = (size_t)row*DM + lane*8;

    float4 v0 = *(float4*)(g_h + base);
    float4 v1 = *(float4*)(g_h + base + 4);
    if (!first) {
        float4 r0 = *(float4*)(g_res + base);
        float4 r1 = *(float4*)(g_res + base + 4);
        v0.x += r0.x; v0.y += r0.y; v0.z += r0.z; v0.w += r0.w;
        v1.x += r1.x; v1.y += r1.y; v1.z += r1.z; v1.w += r1.w;
    }
    *(float4*)(g_res + base)     = v0;
    *(float4*)(g_res + base + 4) = v1;

    float ss = v0.x*v0.x + v0.y*v0.y + v0.z*v0.z + v0.w*v0.w
             + v1.x*v1.x + v1.y*v1.y + v1.z*v1.z + v1.w*v1.w;
    #pragma unroll
    for (int o = 16; o > 0; o >>= 1) ss += __shfl_xor_sync(0xffffffffu, ss, o);
    float sc = rsqrtf(ss * (1.f/DM) + 1e-5f);

    float4 w0 = *(const float4*)(w + lane*8);
    float4 w1 = *(const float4*)(w + lane*8 + 4);
    v0.x *= sc*w0.x; v0.y *= sc*w0.y; v0.z *= sc*w0.z; v0.w *= sc*w0.w;
    v1.x *= sc*w1.x; v1.y *= sc*w1.y; v1.z *= sc*w1.z; v1.w *= sc*w1.w;
    *(float4*)(g_hn + base)     = v0;
    *(float4*)(g_hn + base + 4) = v1;
}

// ---------------------------------------------------------------------------
// TF32 tensor-core GEMM (R5-proven body): C[M,N] = A[M,K] @ W[N,K]^T
// BMx128 tile, BK=16, BM*2 threads, warp tile 32x64.
// MODE 0: plain store. MODE 1: silu on cols >= DI. MODE 2: dt|B|C epilogue
//         (stores g_dt for fallback, g_ce=(dt*xc, exp(-dt)) for scans).
// ---------------------------------------------------------------------------
#define TFS 136
template<int MODE, int BM>
__global__ __launch_bounds__(BM*2)
void tgemm_k(const float* __restrict__ A, int lda,
             const float* __restrict__ W,
             float* __restrict__ C, int ldc,
             int N, int K, const float* __restrict__ bias) {
    constexpr int TH  = BM*2;
    constexpr int RQ  = TH/4;       // rows covered per load batch
    constexpr int AIT = BM/RQ;      // = 2
    constexpr int WIT = 128/RQ;     // 2 (BM=128) or 4 (BM=64)
    __shared__ uint32_t As[16][BM + 8];
    __shared__ uint32_t Ws[16][TFS];
    const int tid  = threadIdx.x;
    const int lane = tid & 31, warp = tid >> 5;
    const int wm = warp >> 1, wn = warp & 1;
    const int lg = lane >> 2, lt = lane & 3;
    const int m0 = blockIdx.y * BM, n0 = blockIdx.x * 128;
    const int ar = tid >> 2, ac = (tid & 3) * 4;

    float acc[2][8][4];
    #pragma unroll
    for (int mt = 0; mt < 2; mt++)
        #pragma unroll
        for (int nt = 0; nt < 8; nt++)
            #pragma unroll
            for (int q = 0; q < 4; q++) acc[mt][nt][q] = 0.f;

    float4 av[AIT], wv[WIT];
    // prologue loads (k0 = 0)
    #pragma unroll
    for (int i = 0; i < AIT; i++)
        av[i] = *(const float4*)(A + (size_t)(m0 + ar + i*RQ)*lda + ac);
    #pragma unroll
    for (int i = 0; i < WIT; i++) {
        int r = n0 + ar + i*RQ;
        wv[i] = (r < N) ? *(const float4*)(W + (size_t)r*K + ac)
                        : make_float4(0.f,0.f,0.f,0.f);
    }

    for (int k0 = 0; k0 < K; k0 += 16) {
        __syncthreads();
        #pragma unroll
        for (int i = 0; i < AIT; i++) {
            int r = ar + i*RQ;
            As[ac+0][r] = f2tf(av[i].x); As[ac+1][r] = f2tf(av[i].y);
            As[ac+2][r] = f2tf(av[i].z); As[ac+3][r] = f2tf(av[i].w);
        }
        #pragma unroll
        for (int i = 0; i < WIT; i++) {
            int r = ar + i*RQ;
            Ws[ac+0][r] = f2tf(wv[i].x); Ws[ac+1][r] = f2tf(wv[i].y);
            Ws[ac+2][r] = f2tf(wv[i].z); Ws[ac+3][r] = f2tf(wv[i].w);
        }
        __syncthreads();

        int kn = k0 + 16;
        if (kn < K) {   // prefetch next tile, overlapped with MMAs below
            #pragma unroll
            for (int i = 0; i < AIT; i++)
                av[i] = *(const float4*)(A + (size_t)(m0 + ar + i*RQ)*lda + kn + ac);
            #pragma unroll
            for (int i = 0; i < WIT; i++) {
                int r = n0 + ar + i*RQ;
                wv[i] = (r < N) ? *(const float4*)(W + (size_t)r*K + kn + ac)
                                : make_float4(0.f,0.f,0.f,0.f);
            }
        }

        #pragma unroll
        for (int ks = 0; ks < 16; ks += 8) {
            uint32_t a[2][4], b[8][2];
            #pragma unroll
            for (int mt = 0; mt < 2; mt++) {
                int mb = wm*32 + mt*16;
                a[mt][0] = As[ks+lt  ][mb+lg];
                a[mt][1] = As[ks+lt  ][mb+lg+8];
                a[mt][2] = As[ks+lt+4][mb+lg];
                a[mt][3] = As[ks+lt+4][mb+lg+8];
            }
            #pragma unroll
            for (int nt = 0; nt < 8; nt++) {
                int nb = wn*64 + nt*8;
                b[nt][0] = Ws[ks+lt  ][nb+lg];
                b[nt][1] = Ws[ks+lt+4][nb+lg];
            }
            #pragma unroll
            for (int mt = 0; mt < 2; mt++)
                #pragma unroll
                for (int nt = 0; nt < 8; nt++)
                    mma8(acc[mt][nt], a[mt], b[nt]);
        }
    }

    #pragma unroll
    for (int mt = 0; mt < 2; mt++) {
        int m = m0 + wm*32 + mt*16 + lg;
        #pragma unroll
        for (int nt = 0; nt < 8; nt++) {
            int n = n0 + wn*64 + nt*8 + lt*2;
            float c0 = acc[mt][nt][0], c1 = acc[mt][nt][1];
            float c2 = acc[mt][nt][2], c3 = acc[mt][nt][3];
            if (MODE == 0 || MODE == 1) {
                if (MODE == 1 && n0 >= DI) {   // z half: pre-apply silu
                    c0 = fsilu(c0); c1 = fsilu(c1);
                    c2 = fsilu(c2); c3 = fsilu(c3);
                }
                if (n < N) {
                    *(float2*)(C + (size_t)m*ldc + n)     = make_float2(c0, c1);
                    *(float2*)(C + (size_t)(m+8)*ldc + n) = make_float2(c2, c3);
                }
            } else { // MODE 2
                if (n < DI) {
                    float b0 = bias[n], b1 = bias[n+1];
                    float d00 = fsoftplus(c0 + b0), d01 = fsoftplus(c1 + b1);
                    float d10 = fsoftplus(c2 + b0), d11 = fsoftplus(c3 + b1);
                    // dt kept for the exact (non-S4D) fallback scan path
                    *(float2*)(g_dt + (size_t)m*DI + n)     = make_float2(d00, d01);
                    *(float2*)(g_dt + (size_t)(m+8)*DI + n) = make_float2(d10, d11);
                    // (c, E) stream for the scans: c = dt * xc, E = exp(-dt)
                    float2 x0 = *(float2*)(g_xc + (size_t)m*DI + n);
                    float2 x1 = *(float2*)(g_xc + (size_t)(m+8)*DI + n);
                    float4 ce0 = make_float4(d00*x0.x, fexp2(-LOG2E*d00),
                                             d01*x0.y, fexp2(-LOG2E*d01));
                    float4 ce1 = make_float4(d10*x1.x, fexp2(-LOG2E*d10),
                                             d11*x1.y, fexp2(-LOG2E*d11));
                    *(float4*)(g_ce + ((size_t)m*DI + n)*2)     = ce0;
                    *(float4*)(g_ce + ((size_t)(m+8)*DI + n)*2) = ce1;
                } else if (n < N) {
                    int j = n - DI;
                    *(float2*)(g_dbc + (size_t)m*32 + j)     = make_float2(c0, c1);
                    *(float2*)(g_dbc + (size_t)(m+8)*32 + j) = make_float2(c2, c3);
                }
            }
        }
    }
}

// ---------------------------------------------------------------------------
// SIMT GEMM (lm_head only): C[M,N] = A[M,K] @ W[N,K]^T
// ---------------------------------------------------------------------------
__global__ __launch_bounds__(256)
void gemm_k(const float* __restrict__ A, int lda,
            const float* __restrict__ W,
            float* __restrict__ C, int ldc,
            int N, int K) {
    __shared__ float As[8][128];
    __shared__ float Ws[8][128];
    const int tid  = threadIdx.x;
    const int m0   = blockIdx.y * 128;
    const int irow = tid >> 1;
    const int icol = (tid & 1) * 4;
    const int trow = tid >> 4;
    const int tcol = tid & 15;

    float acc[8][8];
    #pragma unroll
    for (int i = 0; i < 8; i++)
        #pragma unroll
        for (int j = 0; j < 8; j++) acc[i][j] = 0.f;

    for (int k0 = 0; k0 < K; k0 += 8) {
        float4 av = *reinterpret_cast<const float4*>(
            A + (size_t)(m0 + irow)*lda + k0 + icol);
        As[icol+0][irow] = av.x; As[icol+1][irow] = av.y;
        As[icol+2][irow] = av.z; As[icol+3][irow] = av.w;
        float4 wv = make_float4(0.f,0.f,0.f,0.f);
        if (irow < N)
            wv = *reinterpret_cast<const float4*>(W + (size_t)irow*K + k0 + icol);
        Ws[icol+0][irow] = wv.x; Ws[icol+1][irow] = wv.y;
        Ws[icol+2][irow] = wv.z; Ws[icol+3][irow] = wv.w;
        __syncthreads();
        #pragma unroll
        for (int kk = 0; kk < 8; kk++) {
            float a[8], b[8];
            #pragma unroll
            for (int i = 0; i < 8; i++) a[i] = As[kk][trow*8 + i];
            #pragma unroll
            for (int j = 0; j < 8; j++) b[j] = Ws[kk][tcol*8 + j];
            #pragma unroll
            for (int i = 0; i < 8; i++)
                #pragma unroll
                for (int j = 0; j < 8; j++) acc[i][j] += a[i]*b[j];
        }
        __syncthreads();
    }
    #pragma unroll
    for (int i = 0; i < 8; i++) {
        int m = m0 + trow*8 + i;
        #pragma unroll
        for (int j = 0; j < 8; j++) {
            int n = tcol*8 + j;
            if (n < N) C[(size_t)m*ldc + n] = acc[i][j];
        }
    }
}

// ---------------------------------------------------------------------------
// Depthwise causal conv (width 4) + bias + silu. 4 outputs/thread.
// ---------------------------------------------------------------------------
__global__ void conv_k(const float* __restrict__ cw,
                       const float* __restrict__ cb) {
    int rg = blockIdx.x;            // ROWS/4 groups of 4 consecutive l
    int b  = rg >> 9;
    int l0 = (rg & 511) * 4;
    int tid = threadIdx.x;
    #pragma unroll
    for (int dd = 0; dd < 2; dd++) {
        int d = tid + dd*256;
        float w0 = cw[d*4], w1 = cw[d*4+1], w2 = cw[d*4+2], w3 = cw[d*4+3];
        float bia = cb[d];
        float xv[7];
        #pragma unroll
        for (int j = 0; j < 7; j++) {
            int l = l0 - 3 + j;
            xv[j] = (l >= 0) ? g_xz[(size_t)((b<<11) + l)*(2*DI) + d] : 0.f;
        }
        #pragma unroll
        for (int i = 0; i < 4; i++) {
            float acc = bia + w0*xv[i] + w1*xv[i+1] + w2*xv[i+2] + w3*xv[i+3];
            g_xc[(size_t)((b<<11) + l0 + i)*DI + d] = fsilu(acc);
        }
    }
}

// ---------------------------------------------------------------------------
// Selective scan, chunked 2-pass, NC=64 chunks (CT=32), 256 CTAs per pass.
// Fast path reads ONE float2 (c, E) per step; A precomputed by aprep_k.
// ---------------------------------------------------------------------------
__device__ __forceinline__ void powers16(float dA[DS], float E) {
    float e2 = E*E, e4 = e2*e2, e8 = e4*e4;
    dA[0]=E;        dA[1]=e2;        dA[2]=e2*E;        dA[3]=e4;
    dA[4]=e4*E;     dA[5]=e4*e2;     dA[6]=e4*e2*E;     dA[7]=e8;
    dA[8]=e8*E;     dA[9]=e8*e2;     dA[10]=e8*e2*E;    dA[11]=e8*e4;
    dA[12]=e8*e4*E; dA[13]=e8*e4*e2; dA[14]=e8*e4*e2*E; dA[15]=e8*e8;
}

// grid: BB*NC*2 blocks of 256; block covers 256 d-channels of one (b, chunk)
__global__ __launch_bounds__(256)
void scan1_k(int layer) {
    __shared__ float sB[CT][16];
    int bi = blockIdx.x;
    int b     = bi >> 7;                 // NC*2 = 128 blocks per batch
    int chunk = (bi >> 1) & (NC-1);
    int d     = ((bi & 1) << 8) + threadIdx.x;
    int base  = b*LL + chunk*CT;

    {   // stage B columns only (slots 0..15)
        int r = threadIdx.x >> 2, c = (threadIdx.x & 3) * 4;
        if (r < CT)
            *(float4*)&sB[r][c] = *(const float4*)(g_dbc + (size_t)(base+r)*32 + c);
    }
    __syncthreads();

    const bool fast = g_fastf[(size_t)layer*DI + d] > 0.5f;
    float A[DS];
    if (!fast) {
        const float* ap = g_Aall + ((size_t)layer*DI + d)*DS;
        #pragma unroll
        for (int s = 0; s < DS; s++) A[s] = ap[s];
    }

    float h[DS], ap[DS];
    #pragma unroll
    for (int s = 0; s < DS; s++) { h[s] = 0.f; ap[s] = 1.f; }
    float prodE = 1.f;

    const float* cep = g_ce + ((size_t)base*DI + d)*2;
    float2 ce = *(const float2*)cep;
    for (int t = 0; t < CT; t++) {
        float2 cen = make_float2(0.f, 0.f);
        if (t + 1 < CT) cen = *(const float2*)(cep + (size_t)(t+1)*DI*2);
        float dA[DS];
        if (fast) {
            powers16(dA, ce.y);
            prodE *= ce.y;
        } else {
            float dtv = g_dt[(size_t)(base+t)*DI + d];
            #pragma unroll
            for (int s = 0; s < DS; s++) { dA[s] = __expf(A[s]*dtv); ap[s] *= dA[s]; }
        }
        #pragma unroll
        for (int s = 0; s < DS; s++)
            h[s] = dA[s]*h[s] + ce.x*sB[t][s];
        ce = cen;
    }
    if (fast) powers16(ap, prodE);

    size_t idx0 = ((size_t)(b*DI + d)*DS)*NC + chunk;
    #pragma unroll
    for (int s = 0; s < DS; s++) {
        g_ap[idx0 + (size_t)s*NC] = ap[s];
        g_hl[idx0 + (size_t)s*NC] = h[s];
    }
}

// serial scan across NC chunk carries: one thread per (b,d,s)
__global__ void combine_k() {
    int i = blockIdx.x*256 + threadIdx.x;     // 0..BB*DI*DS
    size_t base = (size_t)i * NC;
    float h = 0.f;
    #pragma unroll 8
    for (int c = 0; c < NC; c++) {
        g_hi[base + c] = h;
        h = g_ap[base + c]*h + g_hl[base + c];
    }
}

__global__ __launch_bounds__(256)
void scan2_k(int layer, const float* __restrict__ Dp) {
    __shared__ float sBC[CT][32];
    int bi = blockIdx.x;
    int b     = bi >> 7;
    int chunk = (bi >> 1) & (NC-1);
    int d     = ((bi & 1) << 8) + threadIdx.x;
    int base  = b*LL + chunk*CT;

    for (int i = threadIdx.x; i < CT*8; i += 256) {
        int r = i >> 3, c = (i & 7) * 4;
        *(float4*)&sBC[r][c] = *(const float4*)(g_dbc + (size_t)(base+r)*32 + c);
    }
    __syncthreads();

    const bool fast = g_fastf[(size_t)layer*DI + d] > 0.5f;
    float A[DS];
    if (!fast) {
        const float* ap = g_Aall + ((size_t)layer*DI + d)*DS;
        #pragma unroll
        for (int s = 0; s < DS; s++) A[s] = ap[s];
    }
    float Dd = Dp[d];

    size_t idx0 = ((size_t)(b*DI + d)*DS)*NC + chunk;
    float h[DS];
    #pragma unroll
    for (int s = 0; s < DS; s++) h[s] = g_hi[idx0 + (size_t)s*NC];

    const float* cep = g_ce + ((size_t)base*DI + d)*2;
    float2 ce = *(const float2*)cep;
    float xv  = g_xc[(size_t)base*DI + d];
    for (int t = 0; t < CT; t++) {
        float2 cen = make_float2(0.f, 0.f);
        float xn = 0.f;
        if (t + 1 < CT) {
            cen = *(const float2*)(cep + (size_t)(t+1)*DI*2);
            xn  = g_xc[(size_t)(base+t+1)*DI + d];
        }
        float dA[DS];
        if (fast) {
            powers16(dA, ce.y);
        } else {
            float dtv = g_dt[(size_t)(base+t)*DI + d];
            #pragma unroll
            for (int s = 0; s < DS; s++) dA[s] = __expf(A[s]*dtv);
        }
        float acc = 0.f;
        #pragma unroll
        for (int s = 0; s < DS; s++) {
            h[s] = dA[s]*h[s] + ce.x*sBC[t][s];
            acc += h[s]*sBC[t][16+s];
        }
        size_t row = base + t;
        float zv = g_xz[row*(2*DI) + DI + d];     // already silu'd by in_proj
        g_y[row*DI + d] = (acc + Dd*xv) * zv;
        ce = cen; xv = xn;
    }
}

// ---------------------------------------------------------------------------
// Host side
// ---------------------------------------------------------------------------
extern "C" void kernel_launch(void* const* d_in, const int* in_sizes, int n_in,
                              void* d_out, int out_size) {
    const int*   ids  = (const int*)  d_in[0];
    const float* emb  = (const float*)d_in[1];
    const float* inw  = (const float*)d_in[2];   // (NL, 2*DI, DM)
    const float* cw   = (const float*)d_in[3];   // (NL, DI, 4)
    const float* cb   = (const float*)d_in[4];   // (NL, DI)
    const float* xw   = (const float*)d_in[5];   // (NL, 48, DI)
    const float* dtw  = (const float*)d_in[6];   // (NL, DI, DR)
    const float* dtb  = (const float*)d_in[7];   // (NL, DI)
    const float* alog = (const float*)d_in[8];   // (NL, DI, DS)
    const float* Dp   = (const float*)d_in[9];   // (NL, DI)
    const float* ow   = (const float*)d_in[10];  // (NL, DM, DI)
    const float* nw   = (const float*)d_in[11];  // (NL, DM)
    const float* nfw  = (const float*)d_in[12];  // (DM)
    const float* lmw  = (const float*)d_in[13];  // (20, DM)
    float* out = (float*)d_out;

    float *p_hn, *p_xz, *p_xc, *p_y, *p_h, *p_wall;
    cudaGetSymbolAddress((void**)&p_hn,   g_hn);
    cudaGetSymbolAddress((void**)&p_xz,   g_xz);
    cudaGetSymbolAddress((void**)&p_xc,   g_xc);
    cudaGetSymbolAddress((void**)&p_y,    g_y);
    cudaGetSymbolAddress((void**)&p_h,    g_h);
    cudaGetSymbolAddress((void**)&p_wall, g_wall);

    embed_k<<<ROWS, DM>>>(ids, emb);
    aprep_k<<<NL*DI/256, 256>>>(alog);
    wdt_k<<<NL*NDT*DI/256, 256>>>(xw, dtw);

    for (int l = 0; l < NL; l++) {
        norm_k<<<ROWS/8, 256>>>(nw + (size_t)l*DM, l == 0);

        // in_proj: (4096,256) x (1024,256)^T -> xz, silu on z half
        tgemm_k<1,128><<<dim3(8, 32), 256>>>(p_hn, DM, inw + (size_t)l*2*DI*DM,
                                             p_xz, 2*DI, 2*DI, DM, nullptr);
        // depthwise conv + silu
        conv_k<<<ROWS/4, 256>>>(cw + (size_t)l*DI*4, cb + (size_t)l*DI);

        // fused dt|B|C: (4096,512) x (544,512)^T -> g_dt, g_ce, g_dbc
        tgemm_k<2,64><<<dim3(5, 64), 128>>>(p_xc, DI, p_wall + (size_t)l*NDT*DI,
                                            nullptr, 0, NDT, DI, dtb + (size_t)l*DI);
        // chunked selective scan (NC=64 chunks -> 256 CTAs per pass)
        scan1_k<<<BB*NC*2, 256>>>(l);
        combine_k<<<BB*DI*DS/256, 256>>>();
        scan2_k<<<BB*NC*2, 256>>>(l, Dp + (size_t)l*DI);

        // out_proj: (4096,512) x (256,512)^T -> h
        tgemm_k<0,64><<<dim3(2, 64), 128>>>(p_y, DI, ow + (size_t)l*DM*DI,
                                            p_h, DM, DM, DI, nullptr);
    }

    // final residual + norm + lm_head
    norm_k<<<ROWS/8, 256>>>(nfw, 0);
    gemm_k<<<dim3(1, 32), 256>>>(p_hn, DM, lmw, out, 20, 20, DM);
}

// round 17
// speedup vs baseline: 1.1279x; 1.1279x over previous
#include <cuda_runtime.h>
#include <cuda_bf16.h>
#include <cstdint>

// ---------------------------------------------------------------------------
// Problem constants
// ---------------------------------------------------------------------------
#define BB      2
#define LL      2048
#define ROWS    (BB*LL)        // 4096 tokens
#define DM      256            // d_model
#define DI      512            // d_inner
#define DS      16             // d_state
#define DR      16             // dt_rank
#define NL      16             // layers
#define NC      64             // scan chunks per sequence
#define CT      (LL/NC)        // 32 steps per chunk
#define NDT     544            // fused dt|B|C GEMM width (512 + 32)
#define LOG2E   1.44269504f

// ---------------------------------------------------------------------------
// Scratch (static device allocations — no cudaMalloc allowed)
// ---------------------------------------------------------------------------
__device__ float g_h  [ROWS*DM];     // block output / embedding
__device__ float g_res[ROWS*DM];     // residual stream
__device__ float g_hn [ROWS*DM];     // normed input
__device__ float g_xz [ROWS*2*DI];   // in_proj output (x | silu(z))
__device__ float g_xc [ROWS*DI];     // conv+silu output
__device__ float g_dbc[ROWS*32];     // B | C per token
__device__ float g_dt [ROWS*DI];     // softplus(dt)  (fallback path only)
__device__ float g_ce [ROWS*DI*2];   // (c = dt*x, E = exp(-dt)) interleaved
__device__ float g_y  [ROWS*DI];     // scan output * silu(z)
// scan state, coalesced layout: [(b*NC + chunk)*DI + d]*DS + s
__device__ float g_ap [BB*NC*DI*DS]; // chunk prod(dA)
__device__ float g_hl [BB*NC*DI*DS]; // chunk local h final
__device__ float g_hi [BB*NC*DI*DS]; // chunk initial h
__device__ float g_wall[NL*NDT*DI];  // fused (W_dt | xw_B | xw_C) weights
__device__ float g_Aall[NL*DI*DS];   // precomputed A = -exp(A_log)
__device__ float g_fastf[NL*DI];     // 1.0 if S4D fast path valid for (l,d)

// ---------------------------------------------------------------------------
// FMA-pipe fast math (avoids MUFU bottleneck)
// ---------------------------------------------------------------------------
__device__ __forceinline__ float fexp2(float x) {
    x = fminf(fmaxf(x, -125.f), 127.f);
    float t = x + 12582912.f;              // 1.5 * 2^23 round trick
    int   i = __float_as_int(t) - 0x4B400000;   // rint(x)
    float f = x - (t - 12582912.f);             // frac in [-0.5, 0.5]
    float p = 1.54035304e-4f;
    p = fmaf(p, f, 1.33335581e-3f);
    p = fmaf(p, f, 9.61812911e-3f);
    p = fmaf(p, f, 5.55041087e-2f);
    p = fmaf(p, f, 2.40226507e-1f);
    p = fmaf(p, f, 6.93147181e-1f);
    p = fmaf(p, f, 1.0f);
    return p * __int_as_float((i + 127) << 23);
}
__device__ __forceinline__ float fsilu(float v) {
    return __fdividef(v, 1.f + fexp2(-LOG2E * v));
}
__device__ __forceinline__ float fsoftplus(float v) {
    if (v > 15.f) return v;
    return log1pf(fexp2(LOG2E * v));
}
__device__ __forceinline__ uint32_t f2tf(float f) {
    uint32_t u; asm("cvt.rna.tf32.f32 %0, %1;" : "=r"(u) : "f"(f)); return u;
}
__device__ __forceinline__ void mma8(float* c, const uint32_t* a, const uint32_t* b) {
    asm volatile(
        "mma.sync.aligned.m16n8k8.row.col.f32.tf32.tf32.f32 "
        "{%0,%1,%2,%3}, {%4,%5,%6,%7}, {%8,%9}, {%0,%1,%2,%3};"
        : "+f"(c[0]), "+f"(c[1]), "+f"(c[2]), "+f"(c[3])
        : "r"(a[0]), "r"(a[1]), "r"(a[2]), "r"(a[3]), "r"(b[0]), "r"(b[1]));
}

// ---------------------------------------------------------------------------
// Embedding gather
// ---------------------------------------------------------------------------
__global__ void embed_k(const int* __restrict__ ids,
                        const float* __restrict__ emb) {
    int row = blockIdx.x, t = threadIdx.x;
    g_h[(size_t)row*DM + t] = emb[(size_t)ids[row]*DM + t];
}

// ---------------------------------------------------------------------------
// A precompute: g_Aall = -exp(A_log); g_fastf = S4D pattern check.
// ---------------------------------------------------------------------------
__global__ void aprep_k(const float* __restrict__ A_log) {
    int i = blockIdx.x*256 + threadIdx.x;     // 0..NL*DI
    const float* src = A_log + (size_t)i*DS;
    float A[DS];
    #pragma unroll
    for (int s = 0; s < DS; s++) A[s] = -__expf(src[s]);
    bool fast = fabsf(A[0] + 1.f) <= 1e-4f;
    #pragma unroll
    for (int s = 1; s < DS; s++)
        fast = fast && (fabsf(A[s] - (float)(s+1)*A[0]) <= 1e-3f*fabsf(A[s]));
    #pragma unroll
    for (int s = 0; s < DS; s++) g_Aall[(size_t)i*DS + s] = A[s];
    g_fastf[i] = fast ? 1.f : 0.f;
}

// ---------------------------------------------------------------------------
// Fused weight precompute: W_dt = dtw @ xw[0:16] ; rows 512.. = xw B/C rows
// ---------------------------------------------------------------------------
__global__ void wdt_k(const float* __restrict__ xw,
                      const float* __restrict__ dtw) {
    size_t i = (size_t)blockIdx.x*256 + threadIdx.x;
    int k = (int)(i & (DI-1));
    int n = (int)((i >> 9) % NDT);
    int l = (int)(i / ((size_t)NDT*DI));
    const float* xwl = xw + (size_t)l*48*DI;
    float v;
    if (n < DI) {
        const float* dr = dtw + ((size_t)l*DI + n)*DR;
        v = 0.f;
        #pragma unroll
        for (int r = 0; r < DR; r++) v += dr[r] * xwl[(size_t)r*DI + k];
    } else {
        v = xwl[(size_t)(16 + n - DI)*DI + k];
    }
    g_wall[i] = v;
}

// ---------------------------------------------------------------------------
// residual += h (or res = h when first); hn = rmsnorm(res) * w
// Warp-per-row, float4 I/O, shfl-only reduction.
// ---------------------------------------------------------------------------
__global__ __launch_bounds__(256)
void norm_k(const float* __restrict__ w, int first) {
    int warp = threadIdx.x >> 5, lane = threadIdx.x & 31;
    int row  = blockIdx.x*8 + warp;
    size_t base = (size_t)row*DM + lane*8;

    float4 v0 = *(float4*)(g_h + base);
    float4 v1 = *(float4*)(g_h + base + 4);
    if (!first) {
        float4 r0 = *(float4*)(g_res + base);
        float4 r1 = *(float4*)(g_res + base + 4);
        v0.x += r0.x; v0.y += r0.y; v0.z += r0.z; v0.w += r0.w;
        v1.x += r1.x; v1.y += r1.y; v1.z += r1.z; v1.w += r1.w;
    }
    *(float4*)(g_res + base)     = v0;
    *(float4*)(g_res + base + 4) = v1;

    float ss = v0.x*v0.x + v0.y*v0.y + v0.z*v0.z + v0.w*v0.w
             + v1.x*v1.x + v1.y*v1.y + v1.z*v1.z + v1.w*v1.w;
    #pragma unroll
    for (int o = 16; o > 0; o >>= 1) ss += __shfl_xor_sync(0xffffffffu, ss, o);
    float sc = rsqrtf(ss * (1.f/DM) + 1e-5f);

    float4 w0 = *(const float4*)(w + lane*8);
    float4 w1 = *(const float4*)(w + lane*8 + 4);
    v0.x *= sc*w0.x; v0.y *= sc*w0.y; v0.z *= sc*w0.z; v0.w *= sc*w0.w;
    v1.x *= sc*w1.x; v1.y *= sc*w1.y; v1.z *= sc*w1.z; v1.w *= sc*w1.w;
    *(float4*)(g_hn + base)     = v0;
    *(float4*)(g_hn + base + 4) = v1;
}

// ---------------------------------------------------------------------------
// TF32 tensor-core GEMM (R5-proven body): C[M,N] = A[M,K] @ W[N,K]^T
// BMx128 tile, BK=16, BM*2 threads, warp tile 32x64.
// MODE 0: plain store. MODE 1: silu on cols >= DI. MODE 2: dt|B|C epilogue.
// ---------------------------------------------------------------------------
#define TFS 136
template<int MODE, int BM>
__global__ __launch_bounds__(BM*2)
void tgemm_k(const float* __restrict__ A, int lda,
             const float* __restrict__ W,
             float* __restrict__ C, int ldc,
             int N, int K, const float* __restrict__ bias) {
    constexpr int TH  = BM*2;
    constexpr int RQ  = TH/4;       // rows covered per load batch
    constexpr int AIT = BM/RQ;      // = 2
    constexpr int WIT = 128/RQ;     // 2 (BM=128) or 4 (BM=64)
    __shared__ uint32_t As[16][BM + 8];
    __shared__ uint32_t Ws[16][TFS];
    const int tid  = threadIdx.x;
    const int lane = tid & 31, warp = tid >> 5;
    const int wm = warp >> 1, wn = warp & 1;
    const int lg = lane >> 2, lt = lane & 3;
    const int m0 = blockIdx.y * BM, n0 = blockIdx.x * 128;
    const int ar = tid >> 2, ac = (tid & 3) * 4;

    float acc[2][8][4];
    #pragma unroll
    for (int mt = 0; mt < 2; mt++)
        #pragma unroll
        for (int nt = 0; nt < 8; nt++)
            #pragma unroll
            for (int q = 0; q < 4; q++) acc[mt][nt][q] = 0.f;

    float4 av[AIT], wv[WIT];
    // prologue loads (k0 = 0)
    #pragma unroll
    for (int i = 0; i < AIT; i++)
        av[i] = *(const float4*)(A + (size_t)(m0 + ar + i*RQ)*lda + ac);
    #pragma unroll
    for (int i = 0; i < WIT; i++) {
        int r = n0 + ar + i*RQ;
        wv[i] = (r < N) ? *(const float4*)(W + (size_t)r*K + ac)
                        : make_float4(0.f,0.f,0.f,0.f);
    }

    for (int k0 = 0; k0 < K; k0 += 16) {
        __syncthreads();
        #pragma unroll
        for (int i = 0; i < AIT; i++) {
            int r = ar + i*RQ;
            As[ac+0][r] = f2tf(av[i].x); As[ac+1][r] = f2tf(av[i].y);
            As[ac+2][r] = f2tf(av[i].z); As[ac+3][r] = f2tf(av[i].w);
        }
        #pragma unroll
        for (int i = 0; i < WIT; i++) {
            int r = ar + i*RQ;
            Ws[ac+0][r] = f2tf(wv[i].x); Ws[ac+1][r] = f2tf(wv[i].y);
            Ws[ac+2][r] = f2tf(wv[i].z); Ws[ac+3][r] = f2tf(wv[i].w);
        }
        __syncthreads();

        int kn = k0 + 16;
        if (kn < K) {   // prefetch next tile, overlapped with MMAs below
            #pragma unroll
            for (int i = 0; i < AIT; i++)
                av[i] = *(const float4*)(A + (size_t)(m0 + ar + i*RQ)*lda + kn + ac);
            #pragma unroll
            for (int i = 0; i < WIT; i++) {
                int r = n0 + ar + i*RQ;
                wv[i] = (r < N) ? *(const float4*)(W + (size_t)r*K + kn + ac)
                                : make_float4(0.f,0.f,0.f,0.f);
            }
        }

        #pragma unroll
        for (int ks = 0; ks < 16; ks += 8) {
            uint32_t a[2][4], b[8][2];
            #pragma unroll
            for (int mt = 0; mt < 2; mt++) {
                int mb = wm*32 + mt*16;
                a[mt][0] = As[ks+lt  ][mb+lg];
                a[mt][1] = As[ks+lt  ][mb+lg+8];
                a[mt][2] = As[ks+lt+4][mb+lg];
                a[mt][3] = As[ks+lt+4][mb+lg+8];
            }
            #pragma unroll
            for (int nt = 0; nt < 8; nt++) {
                int nb = wn*64 + nt*8;
                b[nt][0] = Ws[ks+lt  ][nb+lg];
                b[nt][1] = Ws[ks+lt+4][nb+lg];
            }
            #pragma unroll
            for (int mt = 0; mt < 2; mt++)
                #pragma unroll
                for (int nt = 0; nt < 8; nt++)
                    mma8(acc[mt][nt], a[mt], b[nt]);
        }
    }

    #pragma unroll
    for (int mt = 0; mt < 2; mt++) {
        int m = m0 + wm*32 + mt*16 + lg;
        #pragma unroll
        for (int nt = 0; nt < 8; nt++) {
            int n = n0 + wn*64 + nt*8 + lt*2;
            float c0 = acc[mt][nt][0], c1 = acc[mt][nt][1];
            float c2 = acc[mt][nt][2], c3 = acc[mt][nt][3];
            if (MODE == 0 || MODE == 1) {
                if (MODE == 1 && n0 >= DI) {   // z half: pre-apply silu
                    c0 = fsilu(c0); c1 = fsilu(c1);
                    c2 = fsilu(c2); c3 = fsilu(c3);
                }
                if (n < N) {
                    *(float2*)(C + (size_t)m*ldc + n)     = make_float2(c0, c1);
                    *(float2*)(C + (size_t)(m+8)*ldc + n) = make_float2(c2, c3);
                }
            } else { // MODE 2
                if (n < DI) {
                    float b0 = bias[n], b1 = bias[n+1];
                    float d00 = fsoftplus(c0 + b0), d01 = fsoftplus(c1 + b1);
                    float d10 = fsoftplus(c2 + b0), d11 = fsoftplus(c3 + b1);
                    // dt kept for the exact (non-S4D) fallback scan path
                    *(float2*)(g_dt + (size_t)m*DI + n)     = make_float2(d00, d01);
                    *(float2*)(g_dt + (size_t)(m+8)*DI + n) = make_float2(d10, d11);
                    // (c, E) stream for the scans: c = dt * xc, E = exp(-dt)
                    float2 x0 = *(float2*)(g_xc + (size_t)m*DI + n);
                    float2 x1 = *(float2*)(g_xc + (size_t)(m+8)*DI + n);
                    float4 ce0 = make_float4(d00*x0.x, fexp2(-LOG2E*d00),
                                             d01*x0.y, fexp2(-LOG2E*d01));
                    float4 ce1 = make_float4(d10*x1.x, fexp2(-LOG2E*d10),
                                             d11*x1.y, fexp2(-LOG2E*d11));
                    *(float4*)(g_ce + ((size_t)m*DI + n)*2)     = ce0;
                    *(float4*)(g_ce + ((size_t)(m+8)*DI + n)*2) = ce1;
                } else if (n < N) {
                    int j = n - DI;
                    *(float2*)(g_dbc + (size_t)m*32 + j)     = make_float2(c0, c1);
                    *(float2*)(g_dbc + (size_t)(m+8)*32 + j) = make_float2(c2, c3);
                }
            }
        }
    }
}

// ---------------------------------------------------------------------------
// SIMT GEMM (lm_head only): C[M,N] = A[M,K] @ W[N,K]^T
// ---------------------------------------------------------------------------
__global__ __launch_bounds__(256)
void gemm_k(const float* __restrict__ A, int lda,
            const float* __restrict__ W,
            float* __restrict__ C, int ldc,
            int N, int K) {
    __shared__ float As[8][128];
    __shared__ float Ws[8][128];
    const int tid  = threadIdx.x;
    const int m0   = blockIdx.y * 128;
    const int irow = tid >> 1;
    const int icol = (tid & 1) * 4;
    const int trow = tid >> 4;
    const int tcol = tid & 15;

    float acc[8][8];
    #pragma unroll
    for (int i = 0; i < 8; i++)
        #pragma unroll
        for (int j = 0; j < 8; j++) acc[i][j] = 0.f;

    for (int k0 = 0; k0 < K; k0 += 8) {
        float4 av = *reinterpret_cast<const float4*>(
            A + (size_t)(m0 + irow)*lda + k0 + icol);
        As[icol+0][irow] = av.x; As[icol+1][irow] = av.y;
        As[icol+2][irow] = av.z; As[icol+3][irow] = av.w;
        float4 wv = make_float4(0.f,0.f,0.f,0.f);
        if (irow < N)
            wv = *reinterpret_cast<const float4*>(W + (size_t)irow*K + k0 + icol);
        Ws[icol+0][irow] = wv.x; Ws[icol+1][irow] = wv.y;
        Ws[icol+2][irow] = wv.z; Ws[icol+3][irow] = wv.w;
        __syncthreads();
        #pragma unroll
        for (int kk = 0; kk < 8; kk++) {
            float a[8], b[8];
            #pragma unroll
            for (int i = 0; i < 8; i++) a[i] = As[kk][trow*8 + i];
            #pragma unroll
            for (int j = 0; j < 8; j++) b[j] = Ws[kk][tcol*8 + j];
            #pragma unroll
            for (int i = 0; i < 8; i++)
                #pragma unroll
                for (int j = 0; j < 8; j++) acc[i][j] += a[i]*b[j];
        }
        __syncthreads();
    }
    #pragma unroll
    for (int i = 0; i < 8; i++) {
        int m = m0 + trow*8 + i;
        #pragma unroll
        for (int j = 0; j < 8; j++) {
            int n = tcol*8 + j;
            if (n < N) C[(size_t)m*ldc + n] = acc[i][j];
        }
    }
}

// ---------------------------------------------------------------------------
// Depthwise causal conv (width 4) + bias + silu. 4 outputs/thread.
// ---------------------------------------------------------------------------
__global__ void conv_k(const float* __restrict__ cw,
                       const float* __restrict__ cb) {
    int rg = blockIdx.x;            // ROWS/4 groups of 4 consecutive l
    int b  = rg >> 9;
    int l0 = (rg & 511) * 4;
    int tid = threadIdx.x;
    #pragma unroll
    for (int dd = 0; dd < 2; dd++) {
        int d = tid + dd*256;
        float w0 = cw[d*4], w1 = cw[d*4+1], w2 = cw[d*4+2], w3 = cw[d*4+3];
        float bia = cb[d];
        float xv[7];
        #pragma unroll
        for (int j = 0; j < 7; j++) {
            int l = l0 - 3 + j;
            xv[j] = (l >= 0) ? g_xz[(size_t)((b<<11) + l)*(2*DI) + d] : 0.f;
        }
        #pragma unroll
        for (int i = 0; i < 4; i++) {
            float acc = bia + w0*xv[i] + w1*xv[i+1] + w2*xv[i+2] + w3*xv[i+3];
            g_xc[(size_t)((b<<11) + l0 + i)*DI + d] = fsilu(acc);
        }
    }
}

// ---------------------------------------------------------------------------
// Selective scan, chunked 2-pass, NC=64 chunks (CT=32), 256 CTAs per pass.
// Scan-state layout [(b*NC+chunk)*DI+d]*DS+s -> fully coalesced LDG/STG.128.
// ---------------------------------------------------------------------------
__device__ __forceinline__ void powers16(float dA[DS], float E) {
    float e2 = E*E, e4 = e2*e2, e8 = e4*e4;
    dA[0]=E;        dA[1]=e2;        dA[2]=e2*E;        dA[3]=e4;
    dA[4]=e4*E;     dA[5]=e4*e2;     dA[6]=e4*e2*E;     dA[7]=e8;
    dA[8]=e8*E;     dA[9]=e8*e2;     dA[10]=e8*e2*E;    dA[11]=e8*e4;
    dA[12]=e8*e4*E; dA[13]=e8*e4*e2; dA[14]=e8*e4*e2*E; dA[15]=e8*e8;
}

// grid: BB*NC*2 blocks of 256; block covers 256 d-channels of one (b, chunk)
__global__ __launch_bounds__(256)
void scan1_k(int layer) {
    __shared__ float sB[CT][16];
    int bi = blockIdx.x;
    int b     = bi >> 7;                 // NC*2 = 128 blocks per batch
    int chunk = (bi >> 1) & (NC-1);
    int d     = ((bi & 1) << 8) + threadIdx.x;
    int base  = b*LL + chunk*CT;

    {   // stage B columns only (slots 0..15)
        int r = threadIdx.x >> 2, c = (threadIdx.x & 3) * 4;
        if (r < CT)
            *(float4*)&sB[r][c] = *(const float4*)(g_dbc + (size_t)(base+r)*32 + c);
    }
    __syncthreads();

    const bool fast = g_fastf[(size_t)layer*DI + d] > 0.5f;
    float A[DS];
    if (!fast) {
        const float* ap_ = g_Aall + ((size_t)layer*DI + d)*DS;
        #pragma unroll
        for (int s = 0; s < DS; s++) A[s] = ap_[s];
    }

    float h[DS], ap[DS];
    #pragma unroll
    for (int s = 0; s < DS; s++) { h[s] = 0.f; ap[s] = 1.f; }
    float prodE = 1.f;

    const float* cep = g_ce + ((size_t)base*DI + d)*2;
    float2 ce = *(const float2*)cep;
    for (int t = 0; t < CT; t++) {
        float2 cen = make_float2(0.f, 0.f);
        if (t + 1 < CT) cen = *(const float2*)(cep + (size_t)(t+1)*DI*2);
        float dA[DS];
        if (fast) {
            powers16(dA, ce.y);
            prodE *= ce.y;
        } else {
            float dtv = g_dt[(size_t)(base+t)*DI + d];
            #pragma unroll
            for (int s = 0; s < DS; s++) { dA[s] = __expf(A[s]*dtv); ap[s] *= dA[s]; }
        }
        #pragma unroll
        for (int s = 0; s < DS; s++)
            h[s] = dA[s]*h[s] + ce.x*sB[t][s];
        ce = cen;
    }
    if (fast) powers16(ap, prodE);

    // coalesced state stores: 16 consecutive floats per thread
    size_t idx0 = ((size_t)(b*NC + chunk)*DI + d)*DS;
    #pragma unroll
    for (int q = 0; q < 4; q++) {
        *(float4*)(g_ap + idx0 + q*4) = make_float4(ap[q*4], ap[q*4+1], ap[q*4+2], ap[q*4+3]);
        *(float4*)(g_hl + idx0 + q*4) = make_float4(h[q*4],  h[q*4+1],  h[q*4+2],  h[q*4+3]);
    }
}

// serial scan across NC chunk carries: thread handles one (b,d,s);
// warp covers 32 consecutive (d,s) -> 128B coalesced per chunk step.
__global__ void combine_k() {
    int i = blockIdx.x*256 + threadIdx.x;     // 0..BB*DI*DS
    int b   = i / (DI*DS);
    int rem = i - b*(DI*DS);                  // d*DS + s
    size_t base = (size_t)b*NC*DI*DS + rem;
    float h = 0.f;
    #pragma unroll 8
    for (int c = 0; c < NC; c++) {
        size_t off = base + (size_t)c*DI*DS;
        g_hi[off] = h;
        h = g_ap[off]*h + g_hl[off];
    }
}

__global__ __launch_bounds__(256)
void scan2_k(int layer, const float* __restrict__ Dp) {
    __shared__ float sBC[CT][32];
    int bi = blockIdx.x;
    int b     = bi >> 7;
    int chunk = (bi >> 1) & (NC-1);
    int d     = ((bi & 1) << 8) + threadIdx.x;
    int base  = b*LL + chunk*CT;

    for (int i = threadIdx.x; i < CT*8; i += 256) {
        int r = i >> 3, c = (i & 7) * 4;
        *(float4*)&sBC[r][c] = *(const float4*)(g_dbc + (size_t)(base+r)*32 + c);
    }
    __syncthreads();

    const bool fast = g_fastf[(size_t)layer*DI + d] > 0.5f;
    float A[DS];
    if (!fast) {
        const float* ap_ = g_Aall + ((size_t)layer*DI + d)*DS;
        #pragma unroll
        for (int s = 0; s < DS; s++) A[s] = ap_[s];
    }
    float Dd = Dp[d];

    // coalesced h-init loads
    size_t idx0 = ((size_t)(b*NC + chunk)*DI + d)*DS;
    float h[DS];
    #pragma unroll
    for (int q = 0; q < 4; q++) {
        float4 hv = *(const float4*)(g_hi + idx0 + q*4);
        h[q*4] = hv.x; h[q*4+1] = hv.y; h[q*4+2] = hv.z; h[q*4+3] = hv.w;
    }

    const float* cep = g_ce + ((size_t)base*DI + d)*2;
    float2 ce = *(const float2*)cep;
    float xv  = g_xc[(size_t)base*DI + d];
    for (int t = 0; t < CT; t++) {
        float2 cen = make_float2(0.f, 0.f);
        float xn = 0.f;
        if (t + 1 < CT) {
            cen = *(const float2*)(cep + (size_t)(t+1)*DI*2);
            xn  = g_xc[(size_t)(base+t+1)*DI + d];
        }
        float dA[DS];
        if (fast) {
            powers16(dA, ce.y);
        } else {
            float dtv = g_dt[(size_t)(base+t)*DI + d];
            #pragma unroll
            for (int s = 0; s < DS; s++) dA[s] = __expf(A[s]*dtv);
        }
        float acc = 0.f;
        #pragma unroll
        for (int s = 0; s < DS; s++) {
            h[s] = dA[s]*h[s] + ce.x*sBC[t][s];
            acc += h[s]*sBC[t][16+s];
        }
        size_t row = base + t;
        float zv = g_xz[row*(2*DI) + DI + d];     // already silu'd by in_proj
        g_y[row*DI + d] = (acc + Dd*xv) * zv;
        ce = cen; xv = xn;
    }
}

// ---------------------------------------------------------------------------
// Host side
// ---------------------------------------------------------------------------
extern "C" void kernel_launch(void* const* d_in, const int* in_sizes, int n_in,
                              void* d_out, int out_size) {
    const int*   ids  = (const int*)  d_in[0];
    const float* emb  = (const float*)d_in[1];
    const float* inw  = (const float*)d_in[2];   // (NL, 2*DI, DM)
    const float* cw   = (const float*)d_in[3];   // (NL, DI, 4)
    const float* cb   = (const float*)d_in[4];   // (NL, DI)
    const float* xw   = (const float*)d_in[5];   // (NL, 48, DI)
    const float* dtw  = (const float*)d_in[6];   // (NL, DI, DR)
    const float* dtb  = (const float*)d_in[7];   // (NL, DI)
    const float* alog = (const float*)d_in[8];   // (NL, DI, DS)
    const float* Dp   = (const float*)d_in[9];   // (NL, DI)
    const float* ow   = (const float*)d_in[10];  // (NL, DM, DI)
    const float* nw   = (const float*)d_in[11];  // (NL, DM)
    const float* nfw  = (const float*)d_in[12];  // (DM)
    const float* lmw  = (const float*)d_in[13];  // (20, DM)
    float* out = (float*)d_out;

    float *p_hn, *p_xz, *p_xc, *p_y, *p_h, *p_wall;
    cudaGetSymbolAddress((void**)&p_hn,   g_hn);
    cudaGetSymbolAddress((void**)&p_xz,   g_xz);
    cudaGetSymbolAddress((void**)&p_xc,   g_xc);
    cudaGetSymbolAddress((void**)&p_y,    g_y);
    cudaGetSymbolAddress((void**)&p_h,    g_h);
    cudaGetSymbolAddress((void**)&p_wall, g_wall);

    embed_k<<<ROWS, DM>>>(ids, emb);
    aprep_k<<<NL*DI/256, 256>>>(alog);
    wdt_k<<<NL*NDT*DI/256, 256>>>(xw, dtw);

    for (int l = 0; l < NL; l++) {
        norm_k<<<ROWS/8, 256>>>(nw + (size_t)l*DM, l == 0);

        // in_proj: (4096,256) x (1024,256)^T -> xz, silu on z half (BM=64)
        tgemm_k<1,64><<<dim3(8, 64), 128>>>(p_hn, DM, inw + (size_t)l*2*DI*DM,
                                            p_xz, 2*DI, 2*DI, DM, nullptr);
        // depthwise conv + silu
        conv_k<<<ROWS/4, 256>>>(cw + (size_t)l*DI*4, cb + (size_t)l*DI);

        // fused dt|B|C: (4096,512) x (544,512)^T -> g_dt, g_ce, g_dbc
        tgemm_k<2,64><<<dim3(5, 64), 128>>>(p_xc, DI, p_wall + (size_t)l*NDT*DI,
                                            nullptr, 0, NDT, DI, dtb + (size_t)l*DI);
        // chunked selective scan (NC=64 chunks -> 256 CTAs per pass)
        scan1_k<<<BB*NC*2, 256>>>(l);
        combine_k<<<BB*DI*DS/256, 256>>>();
        scan2_k<<<BB*NC*2, 256>>>(l, Dp + (size_t)l*DI);

        // out_proj: (4096,512) x (256,512)^T -> h
        tgemm_k<0,64><<<dim3(2, 64), 128>>>(p_y, DI, ow + (size_t)l*DM*DI,
                                            p_h, DM, DM, DI, nullptr);
    }

    // final residual + norm + lm_head
    norm_k<<<ROWS/8, 256>>>(nfw, 0);
    gemm_k<<<dim3(1, 32), 256>>>(p_hn, DM, lmw, out, 20, 20, DM);
}